// round 7
// baseline (speedup 1.0000x reference)
#include <cuda_runtime.h>
#include <cooperative_groups.h>
#include <stdint.h>

namespace cg = cooperative_groups;

#define NB 64
#define NC 768
#define NN 576
#define NG 3
#define GS 192
#define HC (NC / 2)     // channels per cluster rank = 384
#define NT 512

__device__ float g_gsum[2 * NB * NG * NC];   // [img*NB][3][NC]
__device__ float g_partial[NB];
__device__ int   g_counter;                  // self-resetting

// ---------------------------------------------------------------------------
// Fused kernel: 64 clusters of 2 CTAs; cluster = one batch index b.
// Rank r owns channels [384r, 384r+384). Phase1 -> DSMEM heat combine ->
// rank/label -> phase2 re-read own channels in reverse (L2-resident).
// ---------------------------------------------------------------------------
__global__ void __cluster_dims__(2, 1, 1) __launch_bounds__(NT, 1)
fused_cluster(const float* __restrict__ in0, const float* __restrict__ in1) {
    __shared__ float              heat[NN];    // own half channel-sums
    __shared__ float              heatc[NN];   // combined
    __shared__ unsigned long long keys[NN];
    __shared__ unsigned char      slab[NN];

    cg::cluster_group cl = cg::this_cluster();
    const int r  = (int)cl.block_rank();       // 0|1
    const int b  = blockIdx.x >> 1;
    const int cbase = r * HC;

    const int tid  = threadIdx.x;
    const int w    = tid >> 5;                 // 0..15
    const int lane = tid & 31;

    float* peer_heat = cl.map_shared_rank(heat, r ^ 1);

    for (int it = 0; it < 2; ++it) {
        const float* src = (it ? in1 : in0) + (size_t)b * NC * NN;

        // zero own heat (FULL 576 — stride, 512 threads!)
        for (int i = tid; i < NN; i += NT) heat[i] = 0.f;
        __syncthreads();

        // ---- Phase 1: warp w sums channels c = cbase + w + 16k (k<24)
        float2 acc[9];
#pragma unroll
        for (int j = 0; j < 9; ++j) acc[j] = make_float2(0.f, 0.f);
#pragma unroll 2
        for (int k = 0; k < HC / 16; ++k) {
            const float2* row = (const float2*)(src + (size_t)(cbase + w + 16 * k) * NN);
#pragma unroll
            for (int j = 0; j < 9; ++j) {
                float2 v = row[lane + 32 * j];
                acc[j].x += v.x;
                acc[j].y += v.y;
            }
        }
#pragma unroll
        for (int j = 0; j < 9; ++j) {
            int n = 2 * (lane + 32 * j);
            atomicAdd(&heat[n],     acc[j].x);
            atomicAdd(&heat[n + 1], acc[j].y);
        }
        __syncthreads();

        // ---- Combine halves via DSMEM (stride over all 576)
        cl.sync();                              // both halves ready
        for (int i = tid; i < NN; i += NT) heatc[i] = heat[i] + peer_heat[i];
        __syncthreads();
        cl.sync();                              // peer done reading my heat

        // ---- Unique sort keys: (ordered-uint heat) << 10 | (1023 - n)
        for (int i = tid; i < NN; i += NT) {
            unsigned u = __float_as_uint(heatc[i]);
            u = (u & 0x80000000u) ? ~u : (u | 0x80000000u);
            keys[i] = ((unsigned long long)u << 10) | (unsigned)(1023 - i);
        }
        __syncthreads();

        // ---- Rank + tercile label: warp w owns n in [36w, 36w+36)
        {
            unsigned long long kr[18];
#pragma unroll
            for (int j = 0; j < 18; ++j) kr[j] = keys[lane + 32 * j];
#pragma unroll
            for (int i = 0; i < 36; ++i) {
                int n = 36 * w + i;
                unsigned long long kn = keys[n];
                unsigned cnt = 0;
#pragma unroll
                for (int j = 0; j < 18; ++j) cnt += (kr[j] > kn);
                unsigned rk = __reduce_add_sync(0xffffffffu, cnt);
                if (lane == 0) slab[n] = (unsigned char)(rk / GS);
            }
        }
        __syncthreads();

        // ---- Per-lane label bitmasks (18 fixed positions per lane)
        unsigned bm0 = 0, bm1 = 0;
#pragma unroll
        for (int j = 0; j < 9; ++j) {
            int n = 2 * (lane + 32 * j);
            unsigned char l0 = slab[n], l1 = slab[n + 1];
            bm0 |= ((l0 == 0) ? 1u : 0u) << (2 * j);
            bm0 |= ((l1 == 0) ? 1u : 0u) << (2 * j + 1);
            bm1 |= ((l0 == 1) ? 1u : 0u) << (2 * j);
            bm1 |= ((l1 == 1) ? 1u : 0u) << (2 * j + 1);
        }

        // ---- Phase 2: re-read own channels in REVERSE (freshest in L2 first)
        float* dst = g_gsum + (size_t)(it * NB + b) * NG * NC;
        for (int k = 0; k < HC / 16; ++k) {
            int c = cbase + (HC - 1) - (w + 16 * k);
            const float2* row = (const float2*)(src + (size_t)c * NN);
            float tot = 0.f, s0 = 0.f, s1 = 0.f;
#pragma unroll
            for (int j = 0; j < 9; ++j) {
                float2 v = row[lane + 32 * j];
                tot += v.x + v.y;
                if ((bm0 >> (2 * j)) & 1u)     s0 += v.x;
                if ((bm0 >> (2 * j + 1)) & 1u) s0 += v.y;
                if ((bm1 >> (2 * j)) & 1u)     s1 += v.x;
                if ((bm1 >> (2 * j + 1)) & 1u) s1 += v.y;
            }
#pragma unroll
            for (int o = 16; o; o >>= 1) {
                tot += __shfl_down_sync(0xffffffffu, tot, o);
                s0  += __shfl_down_sync(0xffffffffu, s0, o);
                s1  += __shfl_down_sync(0xffffffffu, s1, o);
            }
            if (lane == 0) {
                dst[c]          = s0;
                dst[NC + c]     = s1;
                dst[2 * NC + c] = tot - s0 - s1;   // 1/192 cancels in L2 norm
            }
        }
        __syncthreads();
    }
}

// ---------------------------------------------------------------------------
// Epilogue: per-b normalize + SSD; last block (atomic) finalizes scalar.
// ---------------------------------------------------------------------------
__device__ __forceinline__ float block_reduce(float v, float* sm) {
#pragma unroll
    for (int o = 16; o; o >>= 1) v += __shfl_down_sync(0xffffffffu, v, o);
    if ((threadIdx.x & 31) == 0) sm[threadIdx.x >> 5] = v;
    __syncthreads();
    if (threadIdx.x < 8) {
        v = sm[threadIdx.x];
#pragma unroll
        for (int o = 4; o; o >>= 1) v += __shfl_down_sync(0x000000ffu, v, o);
        if (threadIdx.x == 0) sm[0] = v;
    }
    __syncthreads();
    float rr = sm[0];
    __syncthreads();
    return rr;
}

__global__ __launch_bounds__(256, 1)
void epilogue_kernel(float* __restrict__ out) {
    __shared__ float sm[8];
    __shared__ int   is_last;
    const int b = blockIdx.x, tid = threadIdx.x;
    const float* v1 = g_gsum + (size_t)b * NG * NC;
    const float* v2 = g_gsum + (size_t)(NB + b) * NG * NC;

    float a[9], c[9];
#pragma unroll
    for (int k = 0; k < 9; ++k) { a[k] = v1[tid + 256 * k]; c[k] = v2[tid + 256 * k]; }

    float ss1 = 0.f, ss2 = 0.f;
#pragma unroll
    for (int k = 0; k < 9; ++k) { ss1 = fmaf(a[k], a[k], ss1); ss2 = fmaf(c[k], c[k], ss2); }
    ss1 = block_reduce(ss1, sm);
    ss2 = block_reduce(ss2, sm);
    float i1 = 1.f / fmaxf(sqrtf(ss1), 1e-12f);
    float i2 = 1.f / fmaxf(sqrtf(ss2), 1e-12f);

    float acc = 0.f;
#pragma unroll
    for (int k = 0; k < 9; ++k) {
        float d = a[k] * i1 - c[k] * i2;
        acc = fmaf(d, d, acc);
    }
    acc = block_reduce(acc, sm);

    if (tid == 0) {
        g_partial[b] = acc;
        __threadfence();
        int prev = atomicAdd(&g_counter, 1);
        if (prev == NB - 1) { g_counter = 0; is_last = 1; }
        else                { is_last = 0; }
    }
    __syncthreads();

    if (is_last && tid < 32) {
        float v = g_partial[tid] + g_partial[tid + 32];
#pragma unroll
        for (int o = 16; o; o >>= 1) v += __shfl_down_sync(0xffffffffu, v, o);
        if (tid == 0) out[0] = v * (1.f / (float)(NB * NG * NC));
    }
}

extern "C" void kernel_launch(void* const* d_in, const int* in_sizes, int n_in,
                              void* d_out, int out_size) {
    const float* in0 = (const float*)d_in[0];
    const float* in1 = (const float*)d_in[1];
    float* out = (float*)d_out;
    (void)in_sizes; (void)n_in; (void)out_size;

    fused_cluster  <<<2 * NB, NT>>>(in0, in1);
    epilogue_kernel<<<NB, 256>>>(out);
}

// round 8
// speedup vs baseline: 1.1937x; 1.1937x over previous
#include <cuda_runtime.h>
#include <cooperative_groups.h>
#include <stdint.h>

namespace cg = cooperative_groups;

#define NB 64
#define NC 768
#define NN 576
#define NG 3
#define GS 192
#define HC (NC / 2)     // channels per cluster rank = 384
#define NT 512

__device__ float g_gsum[2 * NB * NG * NC];   // [img*NB][3][NC]
__device__ float g_partial[NB];
__device__ int   g_counter;                  // self-resetting

// ---------------------------------------------------------------------------
// Fused kernel: 64 clusters of 2 CTAs; cluster = one batch index b.
// Rank r owns channels [384r, 384r+384). Phase1 -> DSMEM heat combine ->
// rank/label -> phase2 re-read own channels in reverse (L2-resident).
// ---------------------------------------------------------------------------
__global__ void __cluster_dims__(2, 1, 1) __launch_bounds__(NT, 1)
fused_cluster(const float* __restrict__ in0, const float* __restrict__ in1) {
    __shared__ float              heat[NN];    // own half channel-sums
    __shared__ float              heatc[NN];   // combined
    __shared__ unsigned long long keys[NN];
    __shared__ unsigned char      slab[NN];

    cg::cluster_group cl = cg::this_cluster();
    const int r  = (int)cl.block_rank();       // 0|1
    const int b  = blockIdx.x >> 1;
    const int cbase = r * HC;

    const int tid  = threadIdx.x;
    const int w    = tid >> 5;                 // 0..15
    const int lane = tid & 31;

    float* peer_heat = cl.map_shared_rank(heat, r ^ 1);

    for (int it = 0; it < 2; ++it) {
        const float* src = (it ? in1 : in0) + (size_t)b * NC * NN;

        // zero own heat (FULL 576 — stride, 512 threads!)
        for (int i = tid; i < NN; i += NT) heat[i] = 0.f;
        __syncthreads();

        // ---- Phase 1: warp w sums channels c = cbase + w + 16k (k<24)
        float2 acc[9];
#pragma unroll
        for (int j = 0; j < 9; ++j) acc[j] = make_float2(0.f, 0.f);
#pragma unroll 2
        for (int k = 0; k < HC / 16; ++k) {
            const float2* row = (const float2*)(src + (size_t)(cbase + w + 16 * k) * NN);
#pragma unroll
            for (int j = 0; j < 9; ++j) {
                float2 v = row[lane + 32 * j];
                acc[j].x += v.x;
                acc[j].y += v.y;
            }
        }
#pragma unroll
        for (int j = 0; j < 9; ++j) {
            int n = 2 * (lane + 32 * j);
            atomicAdd(&heat[n],     acc[j].x);
            atomicAdd(&heat[n + 1], acc[j].y);
        }
        __syncthreads();

        // ---- Combine halves via DSMEM (stride over all 576)
        cl.sync();                              // both halves ready
        for (int i = tid; i < NN; i += NT) heatc[i] = heat[i] + peer_heat[i];
        __syncthreads();
        cl.sync();                              // peer done reading my heat

        // ---- Unique sort keys: (ordered-uint heat) << 10 | (1023 - n)
        for (int i = tid; i < NN; i += NT) {
            unsigned u = __float_as_uint(heatc[i]);
            u = (u & 0x80000000u) ? ~u : (u | 0x80000000u);
            keys[i] = ((unsigned long long)u << 10) | (unsigned)(1023 - i);
        }
        __syncthreads();

        // ---- Rank + tercile label: warp w owns n in [36w, 36w+36)
        {
            unsigned long long kr[18];
#pragma unroll
            for (int j = 0; j < 18; ++j) kr[j] = keys[lane + 32 * j];
#pragma unroll
            for (int i = 0; i < 36; ++i) {
                int n = 36 * w + i;
                unsigned long long kn = keys[n];
                unsigned cnt = 0;
#pragma unroll
                for (int j = 0; j < 18; ++j) cnt += (kr[j] > kn);
                unsigned rk = __reduce_add_sync(0xffffffffu, cnt);
                if (lane == 0) slab[n] = (unsigned char)(rk / GS);
            }
        }
        __syncthreads();

        // ---- Per-lane label bitmasks (18 fixed positions per lane)
        unsigned bm0 = 0, bm1 = 0;
#pragma unroll
        for (int j = 0; j < 9; ++j) {
            int n = 2 * (lane + 32 * j);
            unsigned char l0 = slab[n], l1 = slab[n + 1];
            bm0 |= ((l0 == 0) ? 1u : 0u) << (2 * j);
            bm0 |= ((l1 == 0) ? 1u : 0u) << (2 * j + 1);
            bm1 |= ((l0 == 1) ? 1u : 0u) << (2 * j);
            bm1 |= ((l1 == 1) ? 1u : 0u) << (2 * j + 1);
        }

        // ---- Phase 2: re-read own channels in REVERSE (freshest in L2 first)
        float* dst = g_gsum + (size_t)(it * NB + b) * NG * NC;
        for (int k = 0; k < HC / 16; ++k) {
            int c = cbase + (HC - 1) - (w + 16 * k);
            const float2* row = (const float2*)(src + (size_t)c * NN);
            float tot = 0.f, s0 = 0.f, s1 = 0.f;
#pragma unroll
            for (int j = 0; j < 9; ++j) {
                float2 v = row[lane + 32 * j];
                tot += v.x + v.y;
                if ((bm0 >> (2 * j)) & 1u)     s0 += v.x;
                if ((bm0 >> (2 * j + 1)) & 1u) s0 += v.y;
                if ((bm1 >> (2 * j)) & 1u)     s1 += v.x;
                if ((bm1 >> (2 * j + 1)) & 1u) s1 += v.y;
            }
#pragma unroll
            for (int o = 16; o; o >>= 1) {
                tot += __shfl_down_sync(0xffffffffu, tot, o);
                s0  += __shfl_down_sync(0xffffffffu, s0, o);
                s1  += __shfl_down_sync(0xffffffffu, s1, o);
            }
            if (lane == 0) {
                dst[c]          = s0;
                dst[NC + c]     = s1;
                dst[2 * NC + c] = tot - s0 - s1;   // 1/192 cancels in L2 norm
            }
        }
        __syncthreads();
    }
}

// ---------------------------------------------------------------------------
// Epilogue: per-b normalize + SSD; last block (atomic) finalizes scalar.
// ---------------------------------------------------------------------------
__device__ __forceinline__ float block_reduce(float v, float* sm) {
#pragma unroll
    for (int o = 16; o; o >>= 1) v += __shfl_down_sync(0xffffffffu, v, o);
    if ((threadIdx.x & 31) == 0) sm[threadIdx.x >> 5] = v;
    __syncthreads();
    if (threadIdx.x < 8) {
        v = sm[threadIdx.x];
#pragma unroll
        for (int o = 4; o; o >>= 1) v += __shfl_down_sync(0x000000ffu, v, o);
        if (threadIdx.x == 0) sm[0] = v;
    }
    __syncthreads();
    float rr = sm[0];
    __syncthreads();
    return rr;
}

__global__ __launch_bounds__(256, 1)
void epilogue_kernel(float* __restrict__ out) {
    __shared__ float sm[8];
    __shared__ int   is_last;
    const int b = blockIdx.x, tid = threadIdx.x;
    const float* v1 = g_gsum + (size_t)b * NG * NC;
    const float* v2 = g_gsum + (size_t)(NB + b) * NG * NC;

    float a[9], c[9];
#pragma unroll
    for (int k = 0; k < 9; ++k) { a[k] = v1[tid + 256 * k]; c[k] = v2[tid + 256 * k]; }

    float ss1 = 0.f, ss2 = 0.f;
#pragma unroll
    for (int k = 0; k < 9; ++k) { ss1 = fmaf(a[k], a[k], ss1); ss2 = fmaf(c[k], c[k], ss2); }
    ss1 = block_reduce(ss1, sm);
    ss2 = block_reduce(ss2, sm);
    float i1 = 1.f / fmaxf(sqrtf(ss1), 1e-12f);
    float i2 = 1.f / fmaxf(sqrtf(ss2), 1e-12f);

    float acc = 0.f;
#pragma unroll
    for (int k = 0; k < 9; ++k) {
        float d = a[k] * i1 - c[k] * i2;
        acc = fmaf(d, d, acc);
    }
    acc = block_reduce(acc, sm);

    if (tid == 0) {
        g_partial[b] = acc;
        __threadfence();
        int prev = atomicAdd(&g_counter, 1);
        if (prev == NB - 1) { g_counter = 0; is_last = 1; }
        else                { is_last = 0; }
    }
    __syncthreads();

    if (is_last && tid < 32) {
        float v = g_partial[tid] + g_partial[tid + 32];
#pragma unroll
        for (int o = 16; o; o >>= 1) v += __shfl_down_sync(0xffffffffu, v, o);
        if (tid == 0) out[0] = v * (1.f / (float)(NB * NG * NC));
    }
}

extern "C" void kernel_launch(void* const* d_in, const int* in_sizes, int n_in,
                              void* d_out, int out_size) {
    const float* in0 = (const float*)d_in[0];
    const float* in1 = (const float*)d_in[1];
    float* out = (float*)d_out;
    (void)in_sizes; (void)n_in; (void)out_size;

    fused_cluster  <<<2 * NB, NT>>>(in0, in1);
    epilogue_kernel<<<NB, 256>>>(out);
}

// round 9
// speedup vs baseline: 1.4901x; 1.2483x over previous
#include <cuda_runtime.h>
#include <stdint.h>

#define NB 64
#define NC 768
#define NN 576
#define NG 3
#define GS 192
#define NT 1024
#define NWP 32          // warps per CTA

__device__ float g_gsum[2 * NB * NG * NC];   // [img*NB + b][3*NC]
__device__ float g_partial[NB];
__device__ int   g_pair[NB];                 // per-b arrival flag (self-resetting)
__device__ int   g_counter;                  // final-sum counter (self-resetting)

__device__ __forceinline__ float block_reduce(float v, float* red) {
    const int lane = threadIdx.x & 31, w = threadIdx.x >> 5;
#pragma unroll
    for (int o = 16; o; o >>= 1) v += __shfl_down_sync(0xffffffffu, v, o);
    if (lane == 0) red[w] = v;
    __syncthreads();
    if (threadIdx.x < 32) {
        v = red[threadIdx.x];
#pragma unroll
        for (int o = 16; o; o >>= 1) v += __shfl_down_sync(0xffffffffu, v, o);
        if (threadIdx.x == 0) red[0] = v;
    }
    __syncthreads();
    float r = red[0];
    __syncthreads();
    return r;
}

// ---------------------------------------------------------------------------
// One CTA per (img,b), 32 warps. heat -> rank -> masked group sums.
// Second-arriving CTA of each b pair computes the normalize+SSD inline;
// last of those 64 writes the final scalar.
// ---------------------------------------------------------------------------
__global__ __launch_bounds__(NT, 1)
void fused_kernel(const float* __restrict__ in0, const float* __restrict__ in1,
                  float* __restrict__ out) {
    __shared__ float              heat[NN];
    __shared__ unsigned long long keys[NN];
    __shared__ unsigned char      slab[NN];
    __shared__ float              red[NWP];
    __shared__ int                flags;

    const int ib   = blockIdx.x;               // img*NB + b
    const int b    = ib & (NB - 1);
    const float* src = ((ib >= NB) ? in1 : in0) + (size_t)b * NC * NN;

    const int tid  = threadIdx.x;
    const int w    = tid >> 5;                 // 0..31
    const int lane = tid & 31;

    for (int i = tid; i < NN; i += NT) heat[i] = 0.f;
    __syncthreads();

    // ---- Phase 1: warp w sums channels c = w + 32k (k<24); lanes: 9 float2
    float2 acc[9];
#pragma unroll
    for (int j = 0; j < 9; ++j) acc[j] = make_float2(0.f, 0.f);
#pragma unroll 2
    for (int k = 0; k < NC / NWP; ++k) {
        const float2* row = (const float2*)(src + (size_t)(w + NWP * k) * NN);
#pragma unroll
        for (int j = 0; j < 9; ++j) {
            float2 v = row[lane + 32 * j];
            acc[j].x += v.x;
            acc[j].y += v.y;
        }
    }
#pragma unroll
    for (int j = 0; j < 9; ++j) {
        int n = 2 * (lane + 32 * j);
        atomicAdd(&heat[n],     acc[j].x);
        atomicAdd(&heat[n + 1], acc[j].y);
    }
    __syncthreads();

    // ---- Unique sort keys: (ordered-uint heat) << 10 | (1023 - n)
    for (int i = tid; i < NN; i += NT) {
        unsigned u = __float_as_uint(heat[i]);
        u = (u & 0x80000000u) ? ~u : (u | 0x80000000u);
        keys[i] = ((unsigned long long)u << 10) | (unsigned)(1023 - i);
    }
    __syncthreads();

    // ---- Rank + tercile label: warp w owns n in [18w, 18w+18)
    {
        unsigned long long kr[18];
#pragma unroll
        for (int j = 0; j < 18; ++j) kr[j] = keys[lane + 32 * j];
#pragma unroll
        for (int i = 0; i < 18; ++i) {
            int n = 18 * w + i;
            unsigned long long kn = keys[n];
            unsigned cnt = 0;
#pragma unroll
            for (int j = 0; j < 18; ++j) cnt += (kr[j] > kn);
            unsigned rk = __reduce_add_sync(0xffffffffu, cnt);
            if (lane == 0) slab[n] = (unsigned char)(rk / GS);
        }
    }
    __syncthreads();

    // ---- Per-lane label bitmasks (18 fixed positions per lane)
    unsigned bm0 = 0, bm1 = 0;
#pragma unroll
    for (int j = 0; j < 9; ++j) {
        int n = 2 * (lane + 32 * j);
        unsigned char l0 = slab[n], l1 = slab[n + 1];
        bm0 |= ((l0 == 0) ? 1u : 0u) << (2 * j);
        bm0 |= ((l1 == 0) ? 1u : 0u) << (2 * j + 1);
        bm1 |= ((l0 == 1) ? 1u : 0u) << (2 * j);
        bm1 |= ((l1 == 1) ? 1u : 0u) << (2 * j + 1);
    }

    // ---- Phase 2: reverse channel order; streaming (last-use) loads
    float* dst = g_gsum + (size_t)ib * NG * NC;
    for (int k = 0; k < NC / NWP; ++k) {
        int c = (NC - 1) - (w + NWP * k);
        const float2* row = (const float2*)(src + (size_t)c * NN);
        float tot = 0.f, s0 = 0.f, s1 = 0.f;
#pragma unroll
        for (int j = 0; j < 9; ++j) {
            float2 v = __ldcs(&row[lane + 32 * j]);
            tot += v.x + v.y;
            if ((bm0 >> (2 * j)) & 1u)     s0 += v.x;
            if ((bm0 >> (2 * j + 1)) & 1u) s0 += v.y;
            if ((bm1 >> (2 * j)) & 1u)     s1 += v.x;
            if ((bm1 >> (2 * j + 1)) & 1u) s1 += v.y;
        }
#pragma unroll
        for (int o = 16; o; o >>= 1) {
            tot += __shfl_down_sync(0xffffffffu, tot, o);
            s0  += __shfl_down_sync(0xffffffffu, s0, o);
            s1  += __shfl_down_sync(0xffffffffu, s1, o);
        }
        if (lane == 0) {
            dst[c]          = s0;
            dst[NC + c]     = s1;
            dst[2 * NC + c] = tot - s0 - s1;   // 1/192 mean factor cancels in norm
        }
    }
    __syncthreads();

    // ---- Pairing: second CTA of this b computes normalize + SSD
    if (tid == 0) {
        __threadfence();
        int prev = atomicAdd(&g_pair[b], 1);
        if (prev == 1) { g_pair[b] = 0; flags = 1; }   // self-reset for replay
        else           { flags = 0; }
    }
    __syncthreads();
    if (!flags) return;

    const float* v1 = g_gsum + (size_t)b * NG * NC;          // image 1
    const float* v2 = g_gsum + (size_t)(NB + b) * NG * NC;   // image 2

    float ss1 = 0.f, ss2 = 0.f;
    for (int i = tid; i < NG * NC; i += NT) {
        float a = v1[i], c = v2[i];
        ss1 = fmaf(a, a, ss1);
        ss2 = fmaf(c, c, ss2);
    }
    ss1 = block_reduce(ss1, red);
    ss2 = block_reduce(ss2, red);
    float i1 = 1.f / fmaxf(sqrtf(ss1), 1e-12f);
    float i2 = 1.f / fmaxf(sqrtf(ss2), 1e-12f);

    float acc2 = 0.f;
    for (int i = tid; i < NG * NC; i += NT) {
        float d = v1[i] * i1 - v2[i] * i2;
        acc2 = fmaf(d, d, acc2);
    }
    acc2 = block_reduce(acc2, red);

    if (tid == 0) {
        g_partial[b] = acc2;
        __threadfence();
        int prev = atomicAdd(&g_counter, 1);
        if (prev == NB - 1) { g_counter = 0; flags = 1; }
        else                { flags = 0; }
    }
    __syncthreads();

    if (flags && tid < 32) {
        float v = g_partial[tid] + g_partial[tid + 32];
#pragma unroll
        for (int o = 16; o; o >>= 1) v += __shfl_down_sync(0xffffffffu, v, o);
        if (tid == 0) out[0] = v * (1.f / (float)(NB * NG * NC));
    }
}

extern "C" void kernel_launch(void* const* d_in, const int* in_sizes, int n_in,
                              void* d_out, int out_size) {
    const float* in0 = (const float*)d_in[0];
    const float* in1 = (const float*)d_in[1];
    float* out = (float*)d_out;
    (void)in_sizes; (void)n_in; (void)out_size;

    fused_kernel<<<2 * NB, NT>>>(in0, in1, out);
}